// round 11
// baseline (speedup 1.0000x reference)
#include <cuda_runtime.h>
#include <math.h>
#include <cstdint>

// ---------------- problem constants ----------------
#define N_TOT   65536      // B*H*W
#define K_CB    512
#define KH      256        // codes per half-CTA
#define C_DIM   64
#define B_DIM   64
#define HW      1024

#define TM      64         // rows per tile
#define THREADS 256
#define NTILES  1024
#define NPAIRS  2048       // (tile, half) pairs
#define NCTAS   304        // 2 CTAs per SM (152 SMs)
#define WROW2   258        // wTh row stride (floats): even, bank stride 2

// output layout (floats), concatenation of the reference tuple
#define Q_OFF     0ULL
#define LOSS_OFF  4194304ULL
#define PERP_OFF  4194368ULL
#define ENC_OFF   4194369ULL
#define EIDX_OFF  37748801ULL
#define DIST_OFF  37814337ULL
#define OUT_TOTAL 71368769

// smem layout (float indices)
#define SM_WT   0                      // wTh[64][258] = 16512 floats
#define SM_XR   16512                  // raw x tiles: 2 x 4096 floats (double buffer)
#define SM_WN   (SM_XR + 8192)         // wnorm[256] (this half)
#define SM_XN   (SM_WN + 256)          // xnorm[64]
#define SM_SIDX (SM_XN + 64)           // int sidx[64]
#define SM_RED  (SM_SIDX + 64)         // float red[256]
#define SM_TOTF (SM_RED + 256)
#define SMEM_BYTES (SM_TOTF * 4)       // ~102 KB -> 2 CTAs/SM

__device__ float g_cb[NTILES * 2 * TM];   // per (tile, half, row) best distance
__device__ int   g_ci[NTILES * 2 * TM];   // per (tile, half, row) best global index
__device__ int   g_tick[NTILES];          // per-tile arrival ticket (reset each launch)
__device__ float g_lpart[NTILES];
__device__ int   g_hist [K_CB];           // zero at load; last CTA re-zeroes
__device__ int   g_done;                  // global ticket; last CTA resets

typedef unsigned long long ull;

// ---------------- helpers ----------------
__device__ __forceinline__ ull pack2(float x) {
    ull r; asm("mov.b64 %0, {%1, %1};" : "=l"(r) : "f"(x)); return r;
}
__device__ __forceinline__ void fma2(ull &d, ull a, ull b) {
    asm("fma.rn.f32x2 %0, %1, %2, %3;" : "=l"(d) : "l"(a), "l"(b), "l"(d));
}
__device__ __forceinline__ void unpack2(ull v, float &lo, float &hi) {
    asm("mov.b64 {%0, %1}, %2;" : "=f"(lo), "=f"(hi) : "l"(v));
}
__device__ __forceinline__ uint32_t smem_u32(const void* p) {
    uint32_t a;
    asm("{ .reg .u64 t; cvta.to.shared.u64 t, %1; cvt.u32.u64 %0, t; }" : "=r"(a) : "l"(p));
    return a;
}
#define CP_ASYNC16(sa, gp) asm volatile("cp.async.cg.shared.global [%0], [%1], 16;" :: "r"(sa), "l"(gp))
#define CP_COMMIT()        asm volatile("cp.async.commit_group;" ::: "memory")
#define CP_WAIT1()         asm volatile("cp.async.wait_group 1;" ::: "memory")
#define CP_WAIT0()         asm volatile("cp.async.wait_group 0;" ::: "memory")

// ---------------- single persistent kernel (2 CTAs/SM, split codebook) ----------------
extern "C" __global__ void __launch_bounds__(THREADS, 2)
vq_all(const float* __restrict__ inputs, const float* __restrict__ weight,
       float* __restrict__ out)
{
    extern __shared__ float smem[];
    float* wTh   = smem + SM_WT;       // wTh[c][k_local], this half's codebook transposed
    float* wnorm = smem + SM_WN;
    float* xnorm = smem + SM_XN;
    int*   sidx  = (int*)(smem + SM_SIDX);
    float* red   = smem + SM_RED;

    const uint32_t xr_sa = smem_u32(smem + SM_XR);
    const int tid  = threadIdx.x;
    const int warp = tid >> 5;         // 8 warps; warp = rowg (rows warp*8..+7)
    const int lane = tid & 31;
    const int kb   = 2 * lane;         // local codes kb + 64*jj + {0,1}, jj=0..3
    const int cta  = blockIdx.x;
    const int half0 = cta & 1;         // this CTA's first pair's half

    // ---- prefetch first x tile into raw buffer 0 ----
    {
        const int t0 = (cta) >> 1;     // tile of first pair
        const float* src = inputs + (size_t)(t0 >> 4) * (C_DIM * HW) + (t0 & 15) * 64;
        for (int i = tid; i < 1024; i += THREADS) {
            int c = i >> 2, ro = (i & 3) * 16;   // 4 cp.async per thread... (i>>2 in 0..255)
            // NOTE: need c in 0..63, 16 chunks of 4 floats per c: re-map below
        }
        // proper mapping: 1024 16B-chunks = 64 c x 16 chunks
        for (int i = tid; i < 1024; i += THREADS) {
            int c = i >> 4, ro = (i & 15) * 4;
            CP_ASYNC16(xr_sa + (uint32_t)(c * 64 + ro) * 4, src + (size_t)c * HW + ro);
        }
        CP_COMMIT();
    }

    // ---- one-time: this half's codebook transpose + wnorm ----
    {
        const float* wb = weight + (size_t)half0 * KH * C_DIM;
        for (int i = tid; i < KH * C_DIM; i += THREADS) {
            int k = i >> 6, c = i & 63;
            wTh[c * WROW2 + k] = wb[i];
        }
        __syncthreads();
        float s = 0.f;
        #pragma unroll
        for (int c = 0; c < C_DIM; c++) { float w = wTh[c * WROW2 + tid]; s = fmaf(w, w, s); }
        wnorm[tid] = s;
    }

    // ---- persistent pair loop ----
    int buf = 0;
    for (int p = cta; p < NPAIRS; p += NCTAS) {
        const int t    = p >> 1;
        const int half = p & 1;        // == half0 always (NCTAS even), codebook stays valid

        // prefetch next pair's x tile into the other buffer
        {
            int pn = p + NCTAS; if (pn >= NPAIRS) pn = 0;
            const int tn = pn >> 1;
            const float* src = inputs + (size_t)(tn >> 4) * (C_DIM * HW) + (tn & 15) * 64;
            uint32_t dst = xr_sa + (uint32_t)((buf ^ 1) * 4096) * 4;
            for (int i = tid; i < 1024; i += THREADS) {
                int c = i >> 4, ro = (i & 15) * 4;
                CP_ASYNC16(dst + (uint32_t)(c * 64 + ro) * 4, src + (size_t)c * HW + ro);
            }
            CP_COMMIT();
        }
        CP_WAIT1();
        __syncthreads();

        const float* xrb = smem + SM_XR + buf * 4096;   // raw xs[c][r]

        // xnorm (sequential fmaf rounding)
        if (tid < TM) {
            float s = 0.f;
            #pragma unroll
            for (int c = 0; c < C_DIM; c++) { float x = xrb[c * 64 + tid]; s = fmaf(x, x, s); }
            xnorm[tid] = s;
        }
        __syncthreads();

        // ---- mainloop (round-8 proven form, half-K): 8 rows x 8 codes per thread ----
        ull acc[8][4];
        #pragma unroll
        for (int r = 0; r < 8; r++)
            #pragma unroll
            for (int j = 0; j < 4; j++) acc[r][j] = 0ULL;

        const float* arow = xrb + warp * 8;
        const ull* bbase = (const ull*)(wTh + kb);

        #pragma unroll 4
        for (int c = 0; c < C_DIM; c++) {
            const float4 a0 = *(const float4*)(arow + c * 64);
            const float4 a1 = *(const float4*)(arow + c * 64 + 4);
            ull aa[8];
            aa[0] = pack2(a0.x); aa[1] = pack2(a0.y); aa[2] = pack2(a0.z); aa[3] = pack2(a0.w);
            aa[4] = pack2(a1.x); aa[5] = pack2(a1.y); aa[6] = pack2(a1.z); aa[7] = pack2(a1.w);
            const ull* bp = bbase + (size_t)c * (WROW2 / 2);
            ull bb[4];
            #pragma unroll
            for (int j = 0; j < 4; j++) bb[j] = bp[32 * j];
            #pragma unroll
            for (int r = 0; r < 8; r++)
                #pragma unroll
                for (int j = 0; j < 4; j++) fma2(acc[r][j], aa[r], bb[j]);
        }

        const int n0   = t * TM;
        const int bimg = t >> 4;
        const int p0   = (t & 15) * 64;

        // ---- epilogue: distances (reference rounding), warp argmin over this half ----
        const float INF = __int_as_float(0x7f800000);
        #pragma unroll
        for (int r = 0; r < 8; r++) {
            const int row = warp * 8 + r;
            const int n   = n0 + row;
            const float xn = xnorm[row];

            float best = INF; int bidx = 0;
            float* dptr = out + DIST_OFF + (size_t)n * K_CB + half * KH + kb;
            #pragma unroll
            for (int j = 0; j < 4; j++) {
                float zlo, zhi; unpack2(acc[r][j], zlo, zhi);
                const int kl = kb + 64 * j;
                float dlo = (xn + wnorm[kl])     - 2.0f * zlo;
                float dhi = (xn + wnorm[kl + 1]) - 2.0f * zhi;
                __stcs(dptr + 64 * j,     dlo);
                __stcs(dptr + 64 * j + 1, dhi);
                if (dlo < best) { best = dlo; bidx = kl; }      // ascending k, strict '<'
                if (dhi < best) { best = dhi; bidx = kl + 1; }  // -> lowest index on ties
            }
            #pragma unroll
            for (int off = 16; off > 0; off >>= 1) {
                float ob = __shfl_xor_sync(0xffffffffu, best, off);
                int   oi = __shfl_xor_sync(0xffffffffu, bidx, off);
                if (ob < best || (ob == best && oi < bidx)) { best = ob; bidx = oi; }
            }
            if (lane == 0) {
                g_cb[(t * 2 + half) * TM + row] = best;
                g_ci[(t * 2 + half) * TM + row] = half * KH + bidx;
            }
        }
        __syncthreads();

        // ---- per-tile ticket: second arriving CTA finalizes the tile ----
        __shared__ int s_do;
        if (tid == 0) {
            __threadfence();                       // publish g_cb/g_ci (+ dist stores)
            s_do = (atomicAdd(&g_tick[t], 1) == 1);
        }
        __syncthreads();

        if (s_do) {
            // combine halves (half0 indices all lower -> tie keeps half0)
            if (tid < TM) {
                float b0 = g_cb[(t * 2) * TM + tid], b1 = g_cb[(t * 2 + 1) * TM + tid];
                int   i0 = g_ci[(t * 2) * TM + tid], i1 = g_ci[(t * 2 + 1) * TM + tid];
                int bi = (b1 < b0) ? i1 : i0;
                sidx[tid] = bi;
                out[EIDX_OFF + (size_t)(n0 + tid)] = (float)bi;
                atomicAdd(&g_hist[bi], 1);
            }
            __syncthreads();

            // encodings one-hot rows: float4 interior (k=3..506) + 4 scalars
            {
                float* ebase = out + ENC_OFF + (size_t)n0 * K_CB;
                #pragma unroll
                for (int rr = 0; rr < 8; rr++) {
                    const int row = warp * 8 + rr;
                    const int sv  = sidx[row];
                    float* rbase = ebase + (size_t)row * K_CB;
                    #pragma unroll
                    for (int m = lane; m < 127; m += 32) {
                        const int k = 3 + 4 * m;
                        float4 v;
                        v.x = (sv == k)     ? 1.0f : 0.0f;
                        v.y = (sv == k + 1) ? 1.0f : 0.0f;
                        v.z = (sv == k + 2) ? 1.0f : 0.0f;
                        v.w = (sv == k + 3) ? 1.0f : 0.0f;
                        __stcs((float4*)(rbase + k), v);
                    }
                    if (lane < 3)       rbase[lane] = (sv == lane) ? 1.0f : 0.0f;
                    else if (lane == 3) rbase[511]  = (sv == 511)  ? 1.0f : 0.0f;
                }
            }

            // q_out (straight-through: x + (q - x)) + fused loss partial
            float* qbase = out + (size_t)bimg * (C_DIM * HW) + p0;
            float s = 0.f;
            #pragma unroll
            for (int i = tid; i < 1024; i += THREADS) {
                const int c = i >> 4, p4 = (i & 15) * 4;
                float4 x4 = *(const float4*)(xrb + c * 64 + p4);
                float4 o;
                float d0 = weight[sidx[p4]     * C_DIM + c] - x4.x;   // L2-hot gathers
                float d1 = weight[sidx[p4 + 1] * C_DIM + c] - x4.y;
                float d2 = weight[sidx[p4 + 2] * C_DIM + c] - x4.z;
                float d3 = weight[sidx[p4 + 3] * C_DIM + c] - x4.w;
                o.x = x4.x + d0; o.y = x4.y + d1; o.z = x4.z + d2; o.w = x4.w + d3;
                __stcs((float4*)(qbase + (size_t)c * HW + p4), o);
                s = fmaf(d0, d0, s); s = fmaf(d1, d1, s);
                s = fmaf(d2, d2, s); s = fmaf(d3, d3, s);
            }
            #pragma unroll
            for (int off = 16; off > 0; off >>= 1) s += __shfl_xor_sync(0xffffffffu, s, off);
            if (lane == 0) red[warp] = s;
            __syncthreads();
            if (warp == 0) {
                float v = (lane < 8) ? red[lane] : 0.f;
                #pragma unroll
                for (int off = 4; off > 0; off >>= 1) v += __shfl_xor_sync(0xffffffffu, v, off);
                if (lane == 0) g_lpart[t] = v;
            }
        }
        __syncthreads();          // protect x buffer recycle + smem reuse

        buf ^= 1;
    }
    CP_WAIT0();

    // ---- fused finish: last CTA computes loss + perplexity; resets tickets ----
    __shared__ int s_last;
    if (tid == 0) {
        __threadfence();
        s_last = (atomicAdd(&g_done, 1) == NCTAS - 1);
    }
    __syncthreads();
    if (s_last) {
        if (tid == 0) g_done = 0;
        for (int i = tid; i < NTILES; i += THREADS) g_tick[i] = 0;   // reset for replay
        if (tid < B_DIM) {
            float s = 0.f;
            #pragma unroll
            for (int j = 0; j < 16; j++) s += g_lpart[tid * 16 + j];  // fixed order
            out[LOSS_OFF + tid] = 1.25f * (s * (1.0f / 65536.0f));
        }
        // perplexity: red[tid] = term(tid) + term(tid+256), then tree (order matches
        // the previous 512-thread reduction bit-for-bit)
        int h0 = g_hist[tid], h1 = g_hist[tid + 256];
        g_hist[tid] = 0; g_hist[tid + 256] = 0;
        float pa = (float)h0 * (1.0f / 65536.0f);
        float pb = (float)h1 * (1.0f / 65536.0f);
        red[tid] = (-pa * logf(pa + 1e-10f)) + (-pb * logf(pb + 1e-10f));
        __syncthreads();
        #pragma unroll
        for (int off = 128; off > 0; off >>= 1) {
            if (tid < off) red[tid] += red[tid + off];
            __syncthreads();
        }
        if (tid == 0) out[PERP_OFF] = expf(red[0]);
    }
}

// ---------------- launch ----------------
extern "C" void kernel_launch(void* const* d_in, const int* in_sizes, int n_in,
                              void* d_out, int out_size)
{
    const float* inputs = (const float*)d_in[0];
    const float* weight = (const float*)d_in[1];
    float* out = (float*)d_out;

    if (out_size != OUT_TOTAL) return;

    cudaFuncSetAttribute(vq_all, cudaFuncAttributeMaxDynamicSharedMemorySize, SMEM_BYTES);

    vq_all<<<NCTAS, THREADS, SMEM_BYTES>>>(inputs, weight, out);
}